// round 4
// baseline (speedup 1.0000x reference)
#include <cuda_runtime.h>
#include <cstdint>

// Problem constants
#define B_   8
#define N1_  8192
#define N2_  2048
#define K_   8
#define C1_  64
#define C2_  128
#define CIN_ 131   // C2 + 3
#define H_   128   // MLP widths
#define CAT_ 192   // H + C1

// Scratch for KNN indices (B*N1*K ints = 2 MB). Device global: allocation-free.
__device__ int g_knn[B_ * N1_ * K_];

// ---------------------------------------------------------------------------
// f32x2 helpers (Blackwell packed fp32; FFMA2 only reachable via PTX)
// ---------------------------------------------------------------------------
__device__ __forceinline__ unsigned long long ffma2(unsigned long long a,
                                                    unsigned long long b,
                                                    unsigned long long c) {
    unsigned long long d;
    asm("fma.rn.f32x2 %0, %1, %2, %3;" : "=l"(d) : "l"(a), "l"(b), "l"(c));
    return d;
}
__device__ __forceinline__ unsigned long long dup2(float v) {
    unsigned long long u;
    asm("mov.b64 %0, {%1, %1};" : "=l"(u) : "f"(v));
    return u;
}
__device__ __forceinline__ float2 u2f(unsigned long long u) {
    float2 v;
    asm("mov.b64 {%0, %1}, %2;" : "=f"(v.x), "=f"(v.y) : "l"(u));
    return v;
}

// ---------------------------------------------------------------------------
// Kernel 1: brute-force KNN (top-8 nearest xyz2 points per xyz1 point)
// One thread per query point; xyz2 for the batch staged in shared memory.
// All lanes scan candidates in lockstep -> smem reads are broadcasts.
// ---------------------------------------------------------------------------
__global__ __launch_bounds__(256) void knn_kernel(
    const float* __restrict__ xyz1,
    const float* __restrict__ xyz2) {
    __shared__ float sx[N2_], sy[N2_], sz[N2_];

    const int b = blockIdx.y;
    const int n = blockIdx.x * 256 + threadIdx.x;

    const float* p2 = xyz2 + (size_t)b * N2_ * 3;
    for (int j = threadIdx.x; j < N2_; j += 256) {
        sx[j] = p2[3 * j + 0];
        sy[j] = p2[3 * j + 1];
        sz[j] = p2[3 * j + 2];
    }
    __syncthreads();

    const int g = b * N1_ + n;
    const float qx = xyz1[3 * (size_t)g + 0];
    const float qy = xyz1[3 * (size_t)g + 1];
    const float qz = xyz1[3 * (size_t)g + 2];

    float bd[K_];
    int   bi[K_];
#pragma unroll
    for (int i = 0; i < K_; ++i) { bd[i] = 3.4e38f; bi[i] = 0; }

    for (int j = 0; j < N2_; ++j) {
        const float dx = sx[j] - qx;
        const float dy = sy[j] - qy;
        const float dz = sz[j] - qz;
        const float d = fmaf(dx, dx, fmaf(dy, dy, dz * dz));
        if (d < bd[K_ - 1]) {  // rare path: insert + bubble up (static indices)
            bd[K_ - 1] = d; bi[K_ - 1] = j;
#pragma unroll
            for (int s = K_ - 1; s > 0; --s) {
                if (bd[s] < bd[s - 1]) {
                    const float td = bd[s]; bd[s] = bd[s - 1]; bd[s - 1] = td;
                    const int   ti = bi[s]; bi[s] = bi[s - 1]; bi[s - 1] = ti;
                }
            }
        }
    }

#pragma unroll
    for (int i = 0; i < K_; ++i) g_knn[(size_t)g * K_ + i] = bi[i];
}

// ---------------------------------------------------------------------------
// Kernel 2: fused gather + MLP(131->128)+relu + MLP(128->128)+relu + maxpool(K)
//           + concat(feat1) + MLP(192->128)+relu
//
// Block = 128 threads handles 2 query points. Thread t: point pp = t>>6,
// channel pair c0 = 2*(t&63). Activations live in smem as DUPLICATED f32x2
// pairs so the inner loop is: 1 LDS.64 (broadcast) + 1 FFMA2 per 2 MACs,
// with each weight LDG.64 reused across 8 neighbor rows.
// ---------------------------------------------------------------------------
__global__ __launch_bounds__(128) void fused_mlp_kernel(
    const float* __restrict__ xyz1,
    const float* __restrict__ xyz2,
    const float* __restrict__ feat1,
    const float* __restrict__ feat2,
    const float* __restrict__ W0, const float* __restrict__ b0,
    const float* __restrict__ W1, const float* __restrict__ b1,
    const float* __restrict__ W2, const float* __restrict__ b2,
    float* __restrict__ out) {

    __shared__ unsigned long long a2[2][K_][CIN_ + 1];  // gathered input rows
    __shared__ unsigned long long h2[2][K_][H_];        // hidden after GEMM1
    __shared__ unsigned long long cat2[2][CAT_];        // [pooled(128) | feat1(64)]

    const int t = threadIdx.x;
    const int pid = blockIdx.x;

    // ---- gather phase: both points, all threads ----
#pragma unroll
    for (int pp = 0; pp < 2; ++pp) {
        const int g = pid * 2 + pp;
        const int b = g >> 13;  // N1 = 8192
#pragma unroll
        for (int r = 0; r < K_; ++r) {
            const int j = g_knn[(size_t)g * K_ + r];   // uniform across block
            const float* f2row = feat2 + ((size_t)(b * N2_ + j)) * C2_;
            a2[pp][r][t] = dup2(f2row[t]);             // t in [0,128): coalesced
            if (t < 3) {
                const float d = xyz2[((size_t)(b * N2_ + j)) * 3 + t]
                              - xyz1[(size_t)g * 3 + t];
                a2[pp][r][C2_ + t] = dup2(d);
            }
        }
        if (t < C1_) cat2[pp][H_ + t] = dup2(feat1[(size_t)g * C1_ + t]);
    }
    __syncthreads();

    const int pp = t >> 6;        // which of the 2 points
    const int cp = t & 63;        // channel-pair index: channels 2cp, 2cp+1

    const unsigned long long* W0u = (const unsigned long long*)W0;
    const unsigned long long* W1u = (const unsigned long long*)W1;
    const unsigned long long* W2u = (const unsigned long long*)W2;

    unsigned long long acc[K_];

    // ---- GEMM1: (8 x 131) @ (131 x 128), relu ----
    {
        const unsigned long long bias = ((const unsigned long long*)b0)[cp];
#pragma unroll
        for (int r = 0; r < K_; ++r) acc[r] = bias;
#pragma unroll 4
        for (int k = 0; k < CIN_; ++k) {
            const unsigned long long w = W0u[k * 64 + cp];
#pragma unroll
            for (int r = 0; r < K_; ++r)
                acc[r] = ffma2(a2[pp][r][k], w, acc[r]);
        }
#pragma unroll
        for (int r = 0; r < K_; ++r) {
            float2 v = u2f(acc[r]);
            h2[pp][r][2 * cp]     = dup2(fmaxf(v.x, 0.0f));
            h2[pp][r][2 * cp + 1] = dup2(fmaxf(v.y, 0.0f));
        }
    }
    __syncthreads();

    // ---- GEMM2: (8 x 128) @ (128 x 128), relu + max over K ----
    {
        const unsigned long long bias = ((const unsigned long long*)b1)[cp];
#pragma unroll
        for (int r = 0; r < K_; ++r) acc[r] = bias;
#pragma unroll 4
        for (int k = 0; k < H_; ++k) {
            const unsigned long long w = W1u[k * 64 + cp];
#pragma unroll
            for (int r = 0; r < K_; ++r)
                acc[r] = ffma2(h2[pp][r][k], w, acc[r]);
        }
        // max_r relu(x_r) == max(0, max_r x_r)
        float px = 0.0f, py = 0.0f;
#pragma unroll
        for (int r = 0; r < K_; ++r) {
            float2 v = u2f(acc[r]);
            px = fmaxf(px, v.x);
            py = fmaxf(py, v.y);
        }
        cat2[pp][2 * cp]     = dup2(px);
        cat2[pp][2 * cp + 1] = dup2(py);
    }
    __syncthreads();

    // ---- GEMM3: (1 x 192) @ (192 x 128), relu ----
    {
        unsigned long long acc3 = ((const unsigned long long*)b2)[cp];
#pragma unroll 4
        for (int k = 0; k < CAT_; ++k)
            acc3 = ffma2(cat2[pp][k], W2u[k * 64 + cp], acc3);

        float2 v = u2f(acc3);
        v.x = fmaxf(v.x, 0.0f);
        v.y = fmaxf(v.y, 0.0f);
        const int g = pid * 2 + pp;
        *(float2*)(out + (size_t)g * H_ + 2 * cp) = v;
    }
}

// ---------------------------------------------------------------------------
// Launch
// ---------------------------------------------------------------------------
extern "C" void kernel_launch(void* const* d_in, const int* in_sizes, int n_in,
                              void* d_out, int out_size) {
    const float* xyz1  = (const float*)d_in[0];
    const float* xyz2  = (const float*)d_in[1];
    const float* feat1 = (const float*)d_in[2];
    const float* feat2 = (const float*)d_in[3];
    const float* W0    = (const float*)d_in[4];
    const float* b0    = (const float*)d_in[5];
    const float* W1    = (const float*)d_in[6];
    const float* b1    = (const float*)d_in[7];
    const float* W2    = (const float*)d_in[8];
    const float* b2    = (const float*)d_in[9];
    float* out = (float*)d_out;

    knn_kernel<<<dim3(N1_ / 256, B_), 256>>>(xyz1, xyz2);

    fused_mlp_kernel<<<(B_ * N1_) / 2, 128>>>(
        xyz1, xyz2, feat1, feat2, W0, b0, W1, b1, W2, b2, out);
}